// round 15
// baseline (speedup 1.0000x reference)
#include <cuda_runtime.h>
#include <cuda_bf16.h>
#include <cstdint>

#define NEG_SLOPE 0.2f
#define STEP (2.0f / 255.0f)

typedef unsigned long long ull;

__device__ float g_asrc[131072];
__device__ float g_adst[131072];

#define FMA2(d, a, b, c) \
    asm("fma.rn.f32x2 %0, %1, %2, %3;" : "=l"(d) : "l"(a), "l"(b), "l"(c))
#define DUP2(d, s) \
    asm("mov.b64 %0, {%1, %1};" : "=l"(d) : "r"(__float_as_uint(s)))
#define UNPACK2(lo, hi, s) do { \
    unsigned _ulo, _uhi; \
    asm("mov.b64 {%0, %1}, %2;" : "=r"(_ulo), "=r"(_uhi) : "l"(s)); \
    lo = __uint_as_float(_ulo); hi = __uint_as_float(_uhi); } while (0)

// ---------------------------------------------------------------------------
// K1: per-node a_src = xg.(W@att_src), a_dst = xg.(W@att_dst)   (unchanged)
// ---------------------------------------------------------------------------
__global__ __launch_bounds__(256) void gat_k1(
    const float* __restrict__ x,
    const float* __restrict__ pos_w,
    const float* __restrict__ pos_b,
    const float* __restrict__ lin_w,
    const float* __restrict__ att_src,
    const float* __restrict__ att_dst)
{
    __shared__ float swd[128];
    __shared__ float as_s[64], ad_s[64];
    __shared__ float pw0[64], pw1[64], pb_s[64];
    __shared__ float sc[6];

    const int tid = threadIdx.x;
    const int row = blockIdx.x;
    const int b = row >> 8;
    const int y = row & 255;

    if (tid < 64) {
        as_s[tid] = att_src[tid];
        ad_s[tid] = att_dst[tid];
        pw0[tid]  = pos_w[tid];
        pw1[tid]  = pos_w[64 + tid];
        pb_s[tid] = pos_b[tid];
    }
    __syncthreads();

    if (tid < 64) {
        float s = 0.0f, d = 0.0f;
        const float* lw = lin_w + tid * 64;
        #pragma unroll 8
        for (int co = 0; co < 64; co++) {
            float w = lw[co];
            s = fmaf(w, as_s[co], s);
            d = fmaf(w, ad_s[co], d);
        }
        swd[2 * tid]     = s;
        swd[2 * tid + 1] = d;
    }
    __syncthreads();

    if (tid < 6) {
        const int which = tid % 3;
        const int off   = (tid < 3) ? 0 : 1;
        const float* pv = (which == 0) ? pw0 : (which == 1) ? pw1 : pb_s;
        float acc = 0.0f;
        #pragma unroll 8
        for (int c = 0; c < 64; c++)
            acc = fmaf(pv[c], swd[2 * c + off], acc);
        sc[tid] = acc;
    }
    __syncthreads();

    const float py = -1.0f + (float)y * STEP;
    const float px = -1.0f + (float)tid * STEP;

    ull acc2 = 0ULL;
    const float* xp = x + (((size_t)b << 22) | ((size_t)y << 8)) + tid;
    const ull* wp = (const ull*)swd;
    #pragma unroll 8
    for (int c = 0; c < 64; c++) {
        float v = xp[(size_t)c << 16];
        ull vv; DUP2(vv, v);
        FMA2(acc2, vv, wp[c], acc2);
    }
    float s, d;
    UNPACK2(s, d, acc2);
    s += fmaf(py, sc[0], fmaf(px, sc[1], sc[2]));
    d += fmaf(py, sc[3], fmaf(px, sc[4], sc[5]));

    const int node = (b << 16) + (y << 8) + tid;
    g_asrc[node] = s;
    g_adst[node] = d;
}

// ---------------------------------------------------------------------------
// mma helpers (base PTX, sm_80+)
// ---------------------------------------------------------------------------
__device__ __forceinline__ uint32_t smem_u32(const void* p) {
    uint32_t r;
    asm("{ .reg .u64 t; cvta.to.shared.u64 t, %1; cvt.u32.u64 %0, t; }"
        : "=r"(r) : "l"(p));
    return r;
}
__device__ __forceinline__ void ldm_x4(uint32_t* r, uint32_t a) {
    asm volatile("ldmatrix.sync.aligned.m8n8.x4.shared.b16 {%0,%1,%2,%3}, [%4];"
        : "=r"(r[0]), "=r"(r[1]), "=r"(r[2]), "=r"(r[3]) : "r"(a));
}
__device__ __forceinline__ void ldm_x4_t(uint32_t* r, uint32_t a) {
    asm volatile("ldmatrix.sync.aligned.m8n8.x4.trans.shared.b16 {%0,%1,%2,%3}, [%4];"
        : "=r"(r[0]), "=r"(r[1]), "=r"(r[2]), "=r"(r[3]) : "r"(a));
}
__device__ __forceinline__ void mma16816(float* c, const uint32_t* a,
                                         uint32_t b0, uint32_t b1) {
    asm volatile(
        "mma.sync.aligned.m16n8k16.row.col.f32.bf16.bf16.f32 "
        "{%0,%1,%2,%3}, {%4,%5,%6,%7}, {%8,%9}, {%0,%1,%2,%3};"
        : "+f"(c[0]), "+f"(c[1]), "+f"(c[2]), "+f"(c[3])
        : "r"(a[0]), "r"(a[1]), "r"(a[2]), "r"(a[3]), "r"(b0), "r"(b1));
}

#define ZPITCH 272   // z tiles [c=64][node=128] bf16: 256B data + 16B pad
#define WPITCH 144   // W tiles [co=64][k=64] bf16: 128B data + 16B pad

// ---------------------------------------------------------------------------
// K2: fused, 4-ROW TILES. block = 32 x * 4 y rows = 128 nodes, 256 threads.
//   Warp = 8 channels, 32 x (lane = x). Per channel: load 6 rows x 3 cols
//   (18 LDG) -> 4 outputs = 4.5 LDG/output. node = row*32 + xl; HMMA GEMM
//   unchanged; epilogue derives (y, x) from node.
// ---------------------------------------------------------------------------
__global__ __launch_bounds__(256) void gat_k2(
    const float* __restrict__ x,
    const float* __restrict__ lin_w,
    const float* __restrict__ pos_w,
    const float* __restrict__ pos_b,
    const float* __restrict__ bias,
    float* __restrict__ out)
{
    __shared__ __align__(16) char tileblob[2 * 64 * ZPITCH];  // zh, zl
    __shared__ __align__(16) char wblob[2 * 64 * WPITCH];     // Wh, Wl
    __shared__ float pw0[64], pw1[64], pb_s[64], b_s[64];

    const int tid  = threadIdx.x;
    const int lane = tid & 31;
    const int wid  = tid >> 5;
    const int blk  = blockIdx.x;        // 1024
    const int b   = blk >> 9;
    const int rem = blk & 511;          // 64 y-groups * 8 x-tiles
    const int y0  = (rem >> 3) << 2;    // 4-row group base
    const int x0g = (rem & 7) << 5;     // x tile base (32 wide)

    char* zh_c = tileblob;
    char* zl_c = tileblob + 64 * ZPITCH;
    char* wh_c = wblob;
    char* wl_c = wblob + 64 * WPITCH;

    if (tid < 64) {
        pw0[tid]  = pos_w[tid];
        pw1[tid]  = pos_w[64 + tid];
        pb_s[tid] = pos_b[tid];
        b_s[tid]  = bias[tid];
    }

    // ---- stage W hi/lo: Wh/Wl[co][k] ----
    {
        const int co = tid & 63;
        const int kq = tid >> 6;
        const float* wp = lin_w + co;
        #pragma unroll
        for (int j = 0; j < 8; j++) {
            const int k0 = kq * 16 + 2 * j;
            float w0 = wp[(size_t)k0 * 64];
            float w1 = wp[(size_t)(k0 + 1) * 64];
            __nv_bfloat162 h = __float22bfloat162_rn(make_float2(w0, w1));
            *(uint32_t*)(wh_c + co * WPITCH + k0 * 2) = *(uint32_t*)&h;
            float r0 = w0 - __bfloat162float(h.x);
            float r1 = w1 - __bfloat162float(h.y);
            __nv_bfloat162 l = __float22bfloat162_rn(make_float2(r0, r1));
            *(uint32_t*)(wl_c + co * WPITCH + k0 * 2) = *(uint32_t*)&l;
        }
    }

    // ---- per-thread geometry ----
    const int xl = lane;                // x within tile (warp = 32 x)
    const int xd = x0g + xl;            // global x
    const int c0 = wid * 8;             // 8 channels per warp/thread

    // ---- alpha for 4 rows (36 regs), from direct LDG ----
    float alpha[4][9];
    float spy[4], spx[4];
    {
        // a_src halo: 6 rows x 3 cols
        float as_v[6][3];
        #pragma unroll
        for (int rr = 0; rr < 6; rr++) {
            const int yy = y0 - 1 + rr;
            const bool rok = (unsigned)yy < 256u;
            #pragma unroll
            for (int cx = 0; cx < 3; cx++) {
                const int xs = xd - 1 + cx;
                float v = -1e30f;
                if (rok && (unsigned)xs < 256u)
                    v = g_asrc[(b << 16) + (yy << 8) + xs];
                as_v[rr][cx] = v;
            }
        }

        #pragma unroll
        for (int rr = 0; rr < 4; rr++) {
            const float ad = g_adst[(b << 16) + ((y0 + rr) << 8) + xd];
            float m = -1e30f;
            #pragma unroll
            for (int ry = 0; ry < 3; ry++) {
                #pragma unroll
                for (int cx = 0; cx < 3; cx++) {
                    float e = as_v[rr + ry][cx] + ad;
                    e = (e >= 0.0f) ? e : NEG_SLOPE * e;
                    alpha[rr][ry * 3 + cx] = e;
                    m = fmaxf(m, e);
                }
            }
            float ssum = 0.0f;
            #pragma unroll
            for (int j = 0; j < 9; j++) {
                float p = expf(alpha[rr][j] - m);
                alpha[rr][j] = p;
                ssum += p;
            }
            const float inv = 1.0f / ssum;
            float sy = 0.0f, sx = 0.0f;
            #pragma unroll
            for (int j = 0; j < 9; j++) {
                alpha[rr][j] *= inv;
                const float pyv = -1.0f + (float)(y0 + rr - 1 + j / 3) * STEP;
                const float pxv = -1.0f + (float)(xd - 1 + j % 3) * STEP;
                sy = fmaf(alpha[rr][j], pyv, sy);
                sx = fmaf(alpha[rr][j], pxv, sx);
            }
            spy[rr] = sy;
            spx[rr] = sx;
        }
    }

    // smem written by threads 0-63 (pw*/pb/b, W tiles) read below by all
    __syncthreads();

    // ---- row offsets (relative to row y0): 6 rows, outer two clamped ----
    int roff[6];
    roff[0] = (y0 == 0) ? 0 : -256;
    roff[1] = 0; roff[2] = 256; roff[3] = 512; roff[4] = 768;
    roff[5] = (y0 == 252) ? 768 : 1024;
    const int xm  = (xd - 1 < 0)   ? 0   : xd - 1;
    const int xpp = (xd + 1 > 255) ? 255 : xd + 1;

    const float* cbase = x + ((size_t)b << 22) + ((size_t)c0 << 16)
                       + ((size_t)y0 << 8);

    #pragma unroll 2
    for (int ci = 0; ci < 8; ci++) {
        const int c = c0 + ci;
        const float* cp = cbase + ((size_t)ci << 16);
        const float* pm = cp + xm;
        const float* pc = cp + xd;
        const float* pp = cp + xpp;

        // 6 rows x 3 cols
        float v[6][3];
        #pragma unroll
        for (int rr = 0; rr < 6; rr++) {
            v[rr][0] = pm[roff[rr]];
            v[rr][1] = pc[roff[rr]];
            v[rr][2] = pp[roff[rr]];
        }

        const float w0c = pw0[c], w1c = pw1[c], pbc = pb_s[c];

        #pragma unroll
        for (int rr = 0; rr < 4; rr++) {
            float z = fmaf(w0c, spy[rr], fmaf(w1c, spx[rr], pbc));
            #pragma unroll
            for (int ry = 0; ry < 3; ry++) {
                z = fmaf(alpha[rr][ry * 3 + 0], v[rr + ry][0], z);
                z = fmaf(alpha[rr][ry * 3 + 1], v[rr + ry][1], z);
                z = fmaf(alpha[rr][ry * 3 + 2], v[rr + ry][2], z);
            }
            // node = rr*32 + xl
            __nv_bfloat16 h = __float2bfloat16(z);
            __nv_bfloat16 l = __float2bfloat16(z - __bfloat162float(h));
            const int node = (rr << 5) + xl;
            *(__nv_bfloat16*)(zh_c + c * ZPITCH + node * 2) = h;
            *(__nv_bfloat16*)(zl_c + c * ZPITCH + node * 2) = l;
        }
    }
    __syncthreads();

    // ---- HMMA GEMM (verified, tile = 64co x 128node x 64k) ----
    const int m0 = (wid & 3) << 4;
    const int nb = (wid >> 2) << 6;     // node base 0 or 64

    const uint32_t zh_b = smem_u32(zh_c);
    const uint32_t zl_b = smem_u32(zl_c);
    const uint32_t wh_b = smem_u32(wh_c);
    const uint32_t wl_b = smem_u32(wl_c);

    const uint32_t w_row = (uint32_t)(m0 + (lane & 15)) * WPITCH;
    const uint32_t w_kad = ((lane >> 4) << 3) * 2;
    const uint32_t z_kro = (uint32_t)(lane & 15) * ZPITCH;
    const uint32_t z_nad = ((lane >> 4) << 3) * 2;

    float acc[8][4];
    #pragma unroll
    for (int i = 0; i < 8; i++)
        #pragma unroll
        for (int j = 0; j < 4; j++) acc[i][j] = 0.0f;

    #pragma unroll
    for (int ks = 0; ks < 4; ks++) {
        const int k0 = ks << 4;
        uint32_t ah[4], al[4];
        ldm_x4(ah, wh_b + w_row + (uint32_t)k0 * 2 + w_kad);
        ldm_x4(al, wl_b + w_row + (uint32_t)k0 * 2 + w_kad);

        #pragma unroll
        for (int np = 0; np < 4; np++) {
            const uint32_t n0 = nb + (np << 4);
            const uint32_t zoff = (uint32_t)k0 * ZPITCH + z_kro + n0 * 2 + z_nad;
            uint32_t bh[4], bl[4];
            ldm_x4_t(bh, zh_b + zoff);
            ldm_x4_t(bl, zl_b + zoff);
            mma16816(acc[2 * np],     ah, bh[0], bh[1]);
            mma16816(acc[2 * np + 1], ah, bh[2], bh[3]);
            mma16816(acc[2 * np],     ah, bl[0], bl[1]);
            mma16816(acc[2 * np + 1], ah, bl[2], bl[3]);
            mma16816(acc[2 * np],     al, bh[0], bh[1]);
            mma16816(acc[2 * np + 1], al, bh[2], bh[3]);
        }
    }

    // ---- direct-STG epilogue: node n = nb + nt*8 + 2*(lane&3) + {0,1} ----
    // y = y0 + (n>>5), x = x0g + (n&31); 2-aligned pairs never cross rows.
    {
        const int co_r = m0 + (lane >> 2);
        const float bv0 = b_s[co_r];
        const float bv1 = b_s[co_r + 8];
        float* obp = out + ((size_t)b << 22) + x0g;
        float* r0p = obp + ((size_t)co_r << 16);
        float* r1p = obp + ((size_t)(co_r + 8) << 16);
        #pragma unroll
        for (int nt = 0; nt < 8; nt++) {
            const int n = nb + nt * 8 + 2 * (lane & 3);
            const int yo = (y0 + (n >> 5)) << 8;
            const int xb = n & 31;
            *(float2*)(r0p + yo + xb) = make_float2(acc[nt][0] + bv0, acc[nt][1] + bv0);
            *(float2*)(r1p + yo + xb) = make_float2(acc[nt][2] + bv1, acc[nt][3] + bv1);
        }
    }
}

// ---------------------------------------------------------------------------
extern "C" void kernel_launch(void* const* d_in, const int* in_sizes, int n_in,
                              void* d_out, int out_size)
{
    const float* x       = (const float*)d_in[0];
    const float* pos_w   = (const float*)d_in[1];
    const float* pos_b   = (const float*)d_in[2];
    const float* lin_w   = (const float*)d_in[3];
    const float* att_src = (const float*)d_in[4];
    const float* att_dst = (const float*)d_in[5];
    const float* bias    = (const float*)d_in[6];
    float* out = (float*)d_out;

    gat_k1<<<512, 256>>>(x, pos_w, pos_b, lin_w, att_src, att_dst);
    gat_k2<<<1024, 256>>>(x, lin_w, pos_w, pos_b, bias, out);
}